// round 17
// baseline (speedup 1.0000x reference)
#include <cuda_runtime.h>
#include <cuda_bf16.h>
#include <cstdint>

// ---------------------------------------------------------------------------
// LGNInputLayerCell: i_in[post] += weights[s] * (inputs_t[pre[s]] > 0)
//   d_in[0] : int32  inputs_t [N_SOURCE]   (17400)
//   d_in[1] : int32  indices  [N_SYN, 2]   (post, pre) interleaved
//   d_in[2] : float  weights  [N_SYN]
//   d_in[3] : int32  n_post   (unused; out_size == n_post)
// output: float [n_post]
//
// R16 locked in PDL + 39-reg body at 112.7us (seg_sum 109.6us = scattered-RED
// wavefront floor, invariant across R5/R8/R13/R16 configs). R17: shrink the
// prologue critical path (one scalar store per thread -> 4x parallelism,
// ~391 blocks) so the PDL grid-dep-sync releases sooner.
// ---------------------------------------------------------------------------

#define MASK_WORDS_MAX 2048     // 65536 sources capacity (17400 -> 544 words)
__device__ unsigned int g_active_mask[MASK_WORDS_MAX];

#define THREADS 512

// ---------------------------------------------------------------------------
// Prologue: build active bitmask (ballot, threads [0, n_src32)) + zero the
// poisoned output (one 4B store per thread). Latency-bound, so maximize
// thread-level parallelism and keep the per-thread path minimal.
// ---------------------------------------------------------------------------
__global__ __launch_bounds__(512)
void prologue_kernel(const int* __restrict__ inputs_t,
                     int n_source,
                     float* __restrict__ out, int n_post) {
    const int i = blockIdx.x * blockDim.x + threadIdx.x;

    // --- bitmask build: whole warps inside/outside (round-up-32 bound) ---
    const int n_src32 = (n_source + 31) & ~31;
    if (i < n_src32) {
        int v = (i < n_source) ? inputs_t[i] : 0;
        unsigned int b = __ballot_sync(0xffffffffu, v > 0);
        if ((threadIdx.x & 31) == 0) g_active_mask[i >> 5] = b;
    }

    // --- zero output: one float per thread ---
    if (i < n_post) out[i] = 0.0f;

    cudaTriggerProgrammaticLaunchCompletion();
}

// ---------------------------------------------------------------------------
// Main scatter-reduce: flat grid, 8 synapses/thread (final form).
// Grid-dependency sync FIRST (no registers live across it), then:
// mask -> SMEM, 6 front-batched LDG.128, 8 predicated REDs.
// ---------------------------------------------------------------------------
__global__ __launch_bounds__(THREADS)
void seg_sum_kernel(const int* __restrict__ indices,
                    const float* __restrict__ weights,
                    float* __restrict__ out,
                    int n_syn, int n_words) {
    cudaGridDependencySynchronize();

    __shared__ unsigned int s_mask[MASK_WORDS_MAX];
    {
        const int n_w4 = (n_words + 3) >> 2;
        int4* s4 = reinterpret_cast<int4*>(s_mask);
        const int4* g4 = reinterpret_cast<const int4*>(g_active_mask);
        for (int w = threadIdx.x; w < n_w4; w += THREADS) s4[w] = g4[w];
    }
    __syncthreads();

    const int i    = blockIdx.x * blockDim.x + threadIdx.x;
    const int base = i << 3;                   // 8 synapses per thread
    if (base >= n_syn) return;

    if (base + 8 <= n_syn) {
        const int4*   idx4 = reinterpret_cast<const int4*>(indices);
        const float4* w4   = reinterpret_cast<const float4*>(weights);

        // 6 independent streaming loads, front-batched (MLP 6).
        int4   a0 = __ldg(&idx4[4 * i + 0]);   // (post0,pre0,post1,pre1)
        int4   a1 = __ldg(&idx4[4 * i + 1]);
        int4   a2 = __ldg(&idx4[4 * i + 2]);
        int4   a3 = __ldg(&idx4[4 * i + 3]);
        float4 w0 = __ldg(&w4[2 * i + 0]);
        float4 w1 = __ldg(&w4[2 * i + 1]);

        const unsigned int m0 = s_mask[((unsigned)a0.y) >> 5];
        const unsigned int m1 = s_mask[((unsigned)a0.w) >> 5];
        const unsigned int m2 = s_mask[((unsigned)a1.y) >> 5];
        const unsigned int m3 = s_mask[((unsigned)a1.w) >> 5];
        const unsigned int m4 = s_mask[((unsigned)a2.y) >> 5];
        const unsigned int m5 = s_mask[((unsigned)a2.w) >> 5];
        const unsigned int m6 = s_mask[((unsigned)a3.y) >> 5];
        const unsigned int m7 = s_mask[((unsigned)a3.w) >> 5];

        if ((m0 >> (a0.y & 31)) & 1u) atomicAdd(out + a0.x, w0.x);
        if ((m1 >> (a0.w & 31)) & 1u) atomicAdd(out + a0.z, w0.y);
        if ((m2 >> (a1.y & 31)) & 1u) atomicAdd(out + a1.x, w0.z);
        if ((m3 >> (a1.w & 31)) & 1u) atomicAdd(out + a1.z, w0.w);
        if ((m4 >> (a2.y & 31)) & 1u) atomicAdd(out + a2.x, w1.x);
        if ((m5 >> (a2.w & 31)) & 1u) atomicAdd(out + a2.z, w1.y);
        if ((m6 >> (a3.y & 31)) & 1u) atomicAdd(out + a3.x, w1.z);
        if ((m7 >> (a3.w & 31)) & 1u) atomicAdd(out + a3.z, w1.w);
    } else {
        // scalar tail (last partial group of < 8 synapses)
        for (int j = base; j < n_syn; ++j) {
            int post = indices[2 * j];
            int pre  = indices[2 * j + 1];
            unsigned int m = s_mask[((unsigned)pre) >> 5];
            if ((m >> (pre & 31)) & 1u) atomicAdd(out + post, weights[j]);
        }
    }
}

extern "C" void kernel_launch(void* const* d_in, const int* in_sizes, int n_in,
                              void* d_out, int out_size) {
    const int*   inputs_t = (const int*)d_in[0];
    const int*   indices  = (const int*)d_in[1];
    const float* weights  = (const float*)d_in[2];
    float*       out      = (float*)d_out;

    const int n_source = in_sizes[0];
    const int n_syn    = in_sizes[2];
    const int n_post   = out_size;

    // 1) fused prologue: bitmask + output zeroing (max TLP, short critical path)
    {
        const int n_src32 = (n_source + 31) & ~31;
        const int n_thr   = (n_src32 > n_post) ? n_src32 : n_post;
        prologue_kernel<<<(n_thr + 511) / 512, 512>>>(inputs_t, n_source, out, n_post);
    }

    // 2) scatter-reduce with programmatic dependency on the prologue;
    //    correctness preserved by grid-dep-sync at the kernel top.
    const int n_words = (n_source + 31) >> 5;   // 544 (< 2048)
    const int groups  = (n_syn + 7) >> 3;
    if (groups > 0) {
        cudaLaunchConfig_t cfg = {};
        cfg.gridDim  = dim3((groups + THREADS - 1) / THREADS);
        cfg.blockDim = dim3(THREADS);
        cfg.dynamicSmemBytes = 0;
        cfg.stream = 0;
        cudaLaunchAttribute at[1];
        at[0].id = cudaLaunchAttributeProgrammaticStreamSerialization;
        at[0].val.programmaticStreamSerializationAllowed = 1;
        cfg.attrs = at;
        cfg.numAttrs = 1;
        cudaLaunchKernelEx(&cfg, seg_sum_kernel,
                           indices, weights, out, n_syn, n_words);
    }
}